// round 14
// baseline (speedup 1.0000x reference)
#include <cuda_runtime.h>
#include <cuda_fp16.h>
#include <cstdint>
#include <cstring>

#define T_SEQ 2048
#define D_MODEL 1024
#define NH 16
#define HD 64
#define BATCH 4
#define M_TOT (BATCH * T_SEQ)       // 8192
#define N_QKV (3 * D_MODEL)         // 3072
#define M_HALF (M_TOT / 2)          // 4096

// ---------------- scratch (__device__ globals: allocation-free) -------------
__device__ __half g_qkvh[(size_t)M_TOT * N_QKV];        // 48 MB, fp16 qkv
__device__ __half g_xh[(size_t)M_TOT * D_MODEL];
__device__ __half g_wq[(size_t)N_QKV * D_MODEL];
__device__ __half g_wo[(size_t)D_MODEL * D_MODEL];
__device__ __half g_ah[(size_t)M_TOT * D_MODEL];

// ---------------- helpers ---------------------------------------------------
__device__ __forceinline__ uint32_t smem_u32(const void* p) {
    uint32_t a;
    asm("{ .reg .u64 t; cvta.to.shared.u64 t, %1; cvt.u32.u64 %0, t; }"
        : "=r"(a) : "l"(p));
    return a;
}
__device__ __forceinline__ void cp_async16(uint32_t smem_dst, const void* gmem_src) {
    asm volatile("cp.async.cg.shared.global [%0], [%1], 16;"
                 :: "r"(smem_dst), "l"(gmem_src) : "memory");
}
__device__ __forceinline__ void cp_commit() {
    asm volatile("cp.async.commit_group;" ::: "memory");
}
__device__ __forceinline__ void cp_wait1() {
    asm volatile("cp.async.wait_group 1;" ::: "memory");
}
__device__ __forceinline__ void ldsm_x4(uint32_t addr, uint32_t& r0, uint32_t& r1,
                                        uint32_t& r2, uint32_t& r3) {
    asm volatile("ldmatrix.sync.aligned.m8n8.x4.shared.b16 {%0,%1,%2,%3}, [%4];"
                 : "=r"(r0), "=r"(r1), "=r"(r2), "=r"(r3) : "r"(addr));
}
__device__ __forceinline__ void mma_f16(float* d, const uint32_t* a, const uint32_t* b) {
    asm volatile(
        "mma.sync.aligned.m16n8k16.row.col.f32.f16.f16.f32 "
        "{%0,%1,%2,%3}, {%4,%5,%6,%7}, {%8,%9}, {%0,%1,%2,%3};"
        : "+f"(d[0]), "+f"(d[1]), "+f"(d[2]), "+f"(d[3])
        : "r"(a[0]), "r"(a[1]), "r"(a[2]), "r"(a[3]), "r"(b[0]), "r"(b[1]));
}

// ---------------- fused fp32 -> fp16 convert ---------------------------------
#define NX4 ((M_TOT * D_MODEL) / 4)
#define NWQ4 ((N_QKV * D_MODEL) / 4)
#define NWO4 ((D_MODEL * D_MODEL) / 4)

__global__ __launch_bounds__(256) void conv_all(
    const float* __restrict__ x, const float* __restrict__ wq_in,
    const float* __restrict__ wo_in,
    __half* __restrict__ xh, __half* __restrict__ wqh, __half* __restrict__ woh)
{
    int i = blockIdx.x * blockDim.x + threadIdx.x;
    const float* src; __half* dst; int j;
    if (i < NX4)                       { src = x;     dst = xh;  j = i; }
    else if (i < NX4 + NWQ4)           { src = wq_in; dst = wqh; j = i - NX4; }
    else if (i < NX4 + NWQ4 + NWO4)    { src = wo_in; dst = woh; j = i - NX4 - NWQ4; }
    else return;
    float4 v = ((const float4*)src)[j];
    __half h[4] = {__float2half_rn(v.x), __float2half_rn(v.y),
                   __float2half_rn(v.z), __float2half_rn(v.w)};
    *(uint2*)(dst + 4 * (size_t)j) = *(uint2*)h;
}

// ---------------- HMMA GEMM: CTA 128x256, warp tile 64x64 --------------------
// smem-crossbar model: warp 64x64 -> 128 B of ldsm per HMMA (was 192 at
// 32x64), lifting tensor busy from ~48% to ~67%. 1 CTA/SM, 166 KB smem.
#define KC 64
#define LDROW 144
#define TILE_A_B (128 * LDROW)       // 18432
#define TILE_B_B (256 * LDROW)       // 36864
#define STAGE_B (TILE_A_B + TILE_B_B) // 55296
#define SMEM_BYTES (3 * STAGE_B)     // 165888
#define NCHUNK (1024 / KC)           // 16
#define EPI_STRIDE 260               // floats per stage row

template <typename OT>
__global__ __launch_bounds__(256, 1) void gemm_hmma(
    const __half* __restrict__ A, const __half* __restrict__ Bw,
    const float* __restrict__ bias, OT* __restrict__ C, int N)
{
    extern __shared__ char smem[];
    const int tid  = threadIdx.x;
    const int wid  = tid >> 5, lane = tid & 31;
    const int wm   = wid >> 2, wn = wid & 3;       // 2 x 4 warps, 64x64 each
    const int bn   = blockIdx.x * 256, bm = blockIdx.y * 128;
    const uint32_t sbase = smem_u32(smem);

    const char* gA = (const char*)A  + (size_t)bm * 2048;
    const char* gB = (const char*)Bw + (size_t)bn * 2048;

    // per stage: A 128 rows x 8 chunks (1024 tasks) + B 256 x 8 (2048 tasks)
    // = 3072 tasks / 256 threads = 12 each; i<4 -> A, i>=4 -> B (uniform).
    auto load_stage = [&](int chunk, int slot) {
        const size_t k0b = (size_t)chunk * (KC * 2);
        uint32_t sdst = sbase + slot * STAGE_B;
        #pragma unroll
        for (int i = 0; i < 12; i++) {
            int idx = tid + i * 256;
            if (i < 4) {                           // idx < 1024: A
                int row = idx >> 3, c = idx & 7;
                cp_async16(sdst + row * LDROW + c * 16,
                           gA + (size_t)row * 2048 + k0b + c * 16);
            } else {                               // B
                int j = idx - 1024;
                int row = j >> 3, c = j & 7;
                cp_async16(sdst + TILE_A_B + row * LDROW + c * 16,
                           gB + (size_t)row * 2048 + k0b + c * 16);
            }
        }
    };

    float acc[4][8][4];
    #pragma unroll
    for (int mt = 0; mt < 4; mt++)
        #pragma unroll
        for (int nt = 0; nt < 8; nt++)
            #pragma unroll
            for (int j = 0; j < 4; j++) acc[mt][nt][j] = 0.f;

    const uint32_t a_off = (uint32_t)(wm * 64 + (lane & 15)) * LDROW + (lane >> 4) * 16;
    const uint32_t b_off = (uint32_t)(wn * 64 + ((lane >> 4) & 1) * 8 + (lane & 7)) * LDROW
                         + ((lane >> 3) & 1) * 16;

    load_stage(0, 0); cp_commit();
    load_stage(1, 1); cp_commit();

    for (int c = 0; c < NCHUNK; c++) {
        const int slot = c % 3;
        cp_wait1();                       // chunk c resident
        __syncthreads();                  // everyone done with slot (c+2)%3
        if (c + 2 < NCHUNK) load_stage(c + 2, (c + 2) % 3);
        cp_commit();                      // uniform group accounting

        const uint32_t st = sbase + slot * STAGE_B;
        const uint32_t tA = st, tB = st + TILE_A_B;

        #pragma unroll
        for (int ks = 0; ks < 4; ks++) {
            const uint32_t kb = ks * 32;
            uint32_t aa[4][4], bb[4][4];
            #pragma unroll
            for (int mt = 0; mt < 4; mt++)
                ldsm_x4(tA + a_off + (uint32_t)mt * 16 * LDROW + kb,
                        aa[mt][0], aa[mt][1], aa[mt][2], aa[mt][3]);
            #pragma unroll
            for (int p = 0; p < 4; p++)
                ldsm_x4(tB + b_off + (uint32_t)p * 16 * LDROW + kb,
                        bb[p][0], bb[p][1], bb[p][2], bb[p][3]);
            #pragma unroll
            for (int mt = 0; mt < 4; mt++)
                #pragma unroll
                for (int nt = 0; nt < 8; nt++)
                    mma_f16(acc[mt][nt], aa[mt], &bb[nt >> 1][(nt & 1) * 2]);
        }
    }
    __syncthreads();                      // all compute done before smem reuse

    // epilogue: stage [128][260] -> coalesced stores + bias
    float* stage = (float*)smem;
    #pragma unroll
    for (int mt = 0; mt < 4; mt++)
        #pragma unroll
        for (int nt = 0; nt < 8; nt++) {
            int row = wm * 64 + mt * 16 + (lane >> 2);
            int col = wn * 64 + nt * 8 + (lane & 3) * 2;
            stage[row * EPI_STRIDE + col]           = acc[mt][nt][0];
            stage[row * EPI_STRIDE + col + 1]       = acc[mt][nt][1];
            stage[(row + 8) * EPI_STRIDE + col]     = acc[mt][nt][2];
            stage[(row + 8) * EPI_STRIDE + col + 1] = acc[mt][nt][3];
        }
    __syncthreads();

    // 128 rows x 64 float4 = 8192 tasks / 256 thr = 32 each
    #pragma unroll
    for (int i = 0; i < 32; i++) {
        int idx = tid + i * 256;
        int row = idx >> 6;
        int c4  = (idx & 63) * 4;
        float4 bv = *(const float4*)(bias + bn + c4);
        float ox = stage[row * EPI_STRIDE + c4 + 0] + bv.x;
        float oy = stage[row * EPI_STRIDE + c4 + 1] + bv.y;
        float oz = stage[row * EPI_STRIDE + c4 + 2] + bv.z;
        float ow = stage[row * EPI_STRIDE + c4 + 3] + bv.w;
        if constexpr (sizeof(OT) == 4) {
            float4 o = {ox, oy, oz, ow};
            *(float4*)((float*)C + (size_t)(bm + row) * N + bn + c4) = o;
        } else {
            __half h4[4] = {__float2half_rn(ox), __float2half_rn(oy),
                            __float2half_rn(oz), __float2half_rn(ow)};
            *(uint2*)((__half*)C + (size_t)(bm + row) * N + bn + c4) = *(uint2*)h4;
        }
    }
}

// ---------------- tensor-core local attention (R11, unchanged) ---------------
#define SQK_B 144
#define SPV_B 208
#define AOFF_Q 0
#define AOFF_K (32 * SQK_B)
#define AOFF_V (AOFF_K + 96 * SQK_B)
#define AOFF_P (AOFF_V + 64 * SPV_B)
#define AOFF_MX (AOFF_P + 32 * SPV_B)
#define AOFF_SM (AOFF_MX + 512)
#define ATTN_SMEM (AOFF_SM + 512)

__global__ __launch_bounds__(128) void attn_mma(
    const __half* __restrict__ qkv, __half* __restrict__ outh)
{
    extern __shared__ char asmem[];
    __half* Qs = (__half*)(asmem + AOFF_Q);
    __half* Ks = (__half*)(asmem + AOFF_K);
    __half* Vt = (__half*)(asmem + AOFF_V);
    __half* Ps = (__half*)(asmem + AOFF_P);
    float* maxp = (float*)(asmem + AOFF_MX);
    float* sump = (float*)(asmem + AOFF_SM);

    const int b = blockIdx.z, h = blockIdx.y;
    const int t0 = blockIdx.x * 32;
    const int kbase = t0 - 32;
    const int tid = threadIdx.x;
    const int w = tid >> 5, lane = tid & 31;
    const uint32_t sb = smem_u32(asmem);

    const __half2 qscale = __float2half2_rn(0.125f);
    #pragma unroll
    for (int i = tid; i < 256; i += 128) {
        int row = i >> 3, c = i & 7;
        uint4 v = ((const uint4*)(qkv + ((size_t)(b * T_SEQ + t0 + row)) * N_QKV
                                  + h * HD))[c];
        __half2 hv[4]; memcpy(hv, &v, 16);
        #pragma unroll
        for (int k = 0; k < 4; k++) hv[k] = __hmul2(hv[k], qscale);
        memcpy(&v, hv, 16);
        *(uint4*)((char*)Qs + row * SQK_B + c * 16) = v;
    }
    #pragma unroll
    for (int i = tid; i < 768; i += 128) {
        int row = i >> 3, c = i & 7;
        int tk = kbase + row;
        uint4 v = {0u, 0u, 0u, 0u};
        if (tk >= 0 && tk < T_SEQ)
            v = ((const uint4*)(qkv + ((size_t)(b * T_SEQ + tk)) * N_QKV
                                + D_MODEL + h * HD))[c];
        *(uint4*)((char*)Ks + row * SQK_B + c * 16) = v;
    }
    #pragma unroll
    for (int i = tid; i < 768; i += 128) {
        int row = i >> 3, c = i & 7;
        int tk = kbase + row;
        uint4 v = {0u, 0u, 0u, 0u};
        if (tk >= 0 && tk < T_SEQ)
            v = ((const uint4*)(qkv + ((size_t)(b * T_SEQ + tk)) * N_QKV
                                + 2 * D_MODEL + h * HD))[c];
        __half hv[8]; memcpy(hv, &v, 16);
        #pragma unroll
        for (int d = 0; d < 8; d++)
            *(__half*)((char*)Vt + (c * 8 + d) * SPV_B + row * 2) = hv[d];
    }
    __syncthreads();

    float sc[2][4][4];
    #pragma unroll
    for (int mt = 0; mt < 2; mt++)
        #pragma unroll
        for (int nt = 0; nt < 4; nt++)
            #pragma unroll
            for (int c = 0; c < 4; c++) sc[mt][nt][c] = 0.f;

    const uint32_t a_off = (uint32_t)(lane & 15) * SQK_B + (lane >> 4) * 16;
    const uint32_t b_off = (uint32_t)(((lane >> 4) & 1) * 8 + (lane & 7)) * SQK_B
                         + ((lane >> 3) & 1) * 16;

    if (w < 3) {
        const uint32_t Qb = sb + AOFF_Q;
        const uint32_t Kb = sb + AOFF_K + (uint32_t)w * 32 * SQK_B;
        #pragma unroll
        for (int ks = 0; ks < 4; ks++) {
            const uint32_t kb = ks * 32;
            uint32_t qa[2][4], kb4[2][4];
            #pragma unroll
            for (int mt = 0; mt < 2; mt++)
                ldsm_x4(Qb + a_off + (uint32_t)mt * 16 * SQK_B + kb,
                        qa[mt][0], qa[mt][1], qa[mt][2], qa[mt][3]);
            #pragma unroll
            for (int p = 0; p < 2; p++)
                ldsm_x4(Kb + b_off + (uint32_t)p * 16 * SQK_B + kb,
                        kb4[p][0], kb4[p][1], kb4[p][2], kb4[p][3]);
            #pragma unroll
            for (int mt = 0; mt < 2; mt++)
                #pragma unroll
                for (int nt = 0; nt < 4; nt++)
                    mma_f16(sc[mt][nt], qa[mt], &kb4[nt >> 1][(nt & 1) * 2]);
        }
    }

    float rmax[4] = {-1e30f, -1e30f, -1e30f, -1e30f};
    if (w < 3) {
        #pragma unroll
        for (int mt = 0; mt < 2; mt++)
            #pragma unroll
            for (int nt = 0; nt < 4; nt++) {
                int j0 = w * 32 + nt * 8 + ((lane & 3) << 1);
                #pragma unroll
                for (int c = 0; c < 4; c++) {
                    int j = j0 + (c & 1);
                    int row = mt * 16 + (c >> 1) * 8 + (lane >> 2);
                    int key = kbase + j;
                    bool ok = (j >= row) && (j <= row + 64) && (key >= 0) && (key < T_SEQ);
                    float s = ok ? sc[mt][nt][c] : -1e30f;
                    sc[mt][nt][c] = s;
                    int ri = mt * 2 + (c >> 1);
                    rmax[ri] = fmaxf(rmax[ri], s);
                }
            }
        #pragma unroll
        for (int ri = 0; ri < 4; ri++) {
            rmax[ri] = fmaxf(rmax[ri], __shfl_xor_sync(0xffffffffu, rmax[ri], 1));
            rmax[ri] = fmaxf(rmax[ri], __shfl_xor_sync(0xffffffffu, rmax[ri], 2));
        }
        if ((lane & 3) == 0)
            #pragma unroll
            for (int ri = 0; ri < 4; ri++) {
                int row = (ri >> 1) * 16 + (ri & 1) * 8 + (lane >> 2);
                maxp[row * 4 + w] = rmax[ri];
            }
    } else {
        if ((lane & 3) == 0)
            #pragma unroll
            for (int ri = 0; ri < 4; ri++) {
                int row = (ri >> 1) * 16 + (ri & 1) * 8 + (lane >> 2);
                maxp[row * 4 + 3] = -1e30f;
                sump[row * 4 + 3] = 0.f;
            }
    }
    __syncthreads();

    float gmx[4], rsum[4] = {0.f, 0.f, 0.f, 0.f};
    #pragma unroll
    for (int ri = 0; ri < 4; ri++) {
        int row = (ri >> 1) * 16 + (ri & 1) * 8 + (lane >> 2);
        float4 mp = *(const float4*)&maxp[row * 4];
        gmx[ri] = fmaxf(fmaxf(mp.x, mp.y), fmaxf(mp.z, mp.w));
    }
    if (w < 3) {
        #pragma unroll
        for (int mt = 0; mt < 2; mt++)
            #pragma unroll
            for (int nt = 0; nt < 4; nt++)
                #pragma unroll
                for (int c = 0; c < 4; c++) {
                    int ri = mt * 2 + (c >> 1);
                    float e = __expf(sc[mt][nt][c] - gmx[ri]);
                    sc[mt][nt][c] = e;
                    rsum[ri] += e;
                }
        #pragma unroll
        for (int ri = 0; ri < 4; ri++) {
            rsum[ri] += __shfl_xor_sync(0xffffffffu, rsum[ri], 1);
            rsum[ri] += __shfl_xor_sync(0xffffffffu, rsum[ri], 2);
        }
        if ((lane & 3) == 0)
            #pragma unroll
            for (int ri = 0; ri < 4; ri++) {
                int row = (ri >> 1) * 16 + (ri & 1) * 8 + (lane >> 2);
                sump[row * 4 + w] = rsum[ri];
            }
    }
    __syncthreads();

    if (w < 3) {
        float inv[4];
        #pragma unroll
        for (int ri = 0; ri < 4; ri++) {
            int row = (ri >> 1) * 16 + (ri & 1) * 8 + (lane >> 2);
            float4 sp = *(const float4*)&sump[row * 4];
            inv[ri] = 1.f / (sp.x + sp.y + sp.z + sp.w);
        }
        #pragma unroll
        for (int mt = 0; mt < 2; mt++)
            #pragma unroll
            for (int nt = 0; nt < 4; nt++) {
                int j0 = w * 32 + nt * 8 + ((lane & 3) << 1);
                int rowA = mt * 16 + (lane >> 2);
                __half2 pA = __floats2half2_rn(sc[mt][nt][0] * inv[mt * 2],
                                               sc[mt][nt][1] * inv[mt * 2]);
                __half2 pB = __floats2half2_rn(sc[mt][nt][2] * inv[mt * 2 + 1],
                                               sc[mt][nt][3] * inv[mt * 2 + 1]);
                *(__half2*)((char*)Ps + rowA * SPV_B + j0 * 2) = pA;
                *(__half2*)((char*)Ps + (rowA + 8) * SPV_B + j0 * 2) = pB;
            }
    }
    __syncthreads();

    float oc[2][2][4];
    #pragma unroll
    for (int mt = 0; mt < 2; mt++)
        #pragma unroll
        for (int nt = 0; nt < 2; nt++)
            #pragma unroll
            for (int c = 0; c < 4; c++) oc[mt][nt][c] = 0.f;

    const uint32_t Pb = sb + AOFF_P;
    const uint32_t Vb = sb + AOFF_V + (uint32_t)w * 16 * SPV_B;
    const uint32_t a_offP = (uint32_t)(lane & 15) * SPV_B + (lane >> 4) * 16;
    const uint32_t b_offV = (uint32_t)(((lane >> 4) & 1) * 8 + (lane & 7)) * SPV_B
                          + ((lane >> 3) & 1) * 16;

    #pragma unroll
    for (int ks = 0; ks < 6; ks++) {
        const uint32_t kb = ks * 32;
        uint32_t pa[2][4], vb[4];
        #pragma unroll
        for (int mt = 0; mt < 2; mt++)
            ldsm_x4(Pb + a_offP + (uint32_t)mt * 16 * SPV_B + kb,
                    pa[mt][0], pa[mt][1], pa[mt][2], pa[mt][3]);
        ldsm_x4(Vb + b_offV + kb, vb[0], vb[1], vb[2], vb[3]);
        #pragma unroll
        for (int mt = 0; mt < 2; mt++)
            #pragma unroll
            for (int nt = 0; nt < 2; nt++)
                mma_f16(oc[mt][nt], pa[mt], &vb[nt * 2]);
    }

    const size_t base = ((size_t)(b * T_SEQ + t0)) * D_MODEL + h * HD;
    #pragma unroll
    for (int mt = 0; mt < 2; mt++)
        #pragma unroll
        for (int nt = 0; nt < 2; nt++) {
            int rowA = mt * 16 + (lane >> 2);
            int col = w * 16 + nt * 8 + ((lane & 3) << 1);
            __half2 hA = __floats2half2_rn(oc[mt][nt][0], oc[mt][nt][1]);
            __half2 hB = __floats2half2_rn(oc[mt][nt][2], oc[mt][nt][3]);
            *(__half2*)(outh + base + (size_t)rowA * D_MODEL + col) = hA;
            *(__half2*)(outh + base + (size_t)(rowA + 8) * D_MODEL + col) = hB;
        }
}

// ---------------------------------------------------------------------------
extern "C" void kernel_launch(void* const* d_in, const int* in_sizes, int n_in,
                              void* d_out, int out_size)
{
    const float* x    = (const float*)d_in[0];
    const float* Wqkv = (const float*)d_in[1];
    const float* bqkv = (const float*)d_in[2];
    const float* Wout = (const float*)d_in[3];
    const float* bout = (const float*)d_in[4];
    float* out = (float*)d_out;

    __half *qkvh, *xh, *wq, *wo, *ah;
    cudaGetSymbolAddress((void**)&qkvh, g_qkvh);
    cudaGetSymbolAddress((void**)&xh, g_xh);
    cudaGetSymbolAddress((void**)&wq, g_wq);
    cudaGetSymbolAddress((void**)&wo, g_wo);
    cudaGetSymbolAddress((void**)&ah, g_ah);

    cudaFuncSetAttribute(gemm_hmma<__half>, cudaFuncAttributeMaxDynamicSharedMemorySize, SMEM_BYTES);
    cudaFuncSetAttribute(gemm_hmma<float>,  cudaFuncAttributeMaxDynamicSharedMemorySize, SMEM_BYTES);
    cudaFuncSetAttribute(attn_mma, cudaFuncAttributeMaxDynamicSharedMemorySize, ATTN_SMEM);

    static cudaStream_t s1 = nullptr;
    static cudaEvent_t evA = nullptr, evDone = nullptr;
    if (s1 == nullptr) {
        cudaStreamCreateWithFlags(&s1, cudaStreamNonBlocking);
        cudaEventCreateWithFlags(&evA, cudaEventDisableTiming);
        cudaEventCreateWithFlags(&evDone, cudaEventDisableTiming);
    }

    {
        int total = NX4 + NWQ4 + NWO4;
        conv_all<<<(total + 255) / 256, 256>>>(x, Wqkv, Wout, xh, wq, wo);
    }

    // QKV half A (rows 0..4095)
    gemm_hmma<__half><<<dim3(N_QKV / 256, M_HALF / 128), 256, SMEM_BYTES>>>(
        xh, wq, bqkv, qkvh, N_QKV);
    cudaEventRecord(evA, 0);

    // s1: attention + out-proj for half A, overlapped with s0's half-B QKV
    cudaStreamWaitEvent(s1, evA, 0);
    attn_mma<<<dim3(T_SEQ / 32, NH, BATCH / 2), 128, ATTN_SMEM, s1>>>(qkvh, ah);
    gemm_hmma<float><<<dim3(D_MODEL / 256, M_HALF / 128), 256, SMEM_BYTES, s1>>>(
        ah, wo, bout, out, D_MODEL);
    cudaEventRecord(evDone, s1);

    // s0: QKV half B, then its attention + out-proj
    gemm_hmma<__half><<<dim3(N_QKV / 256, M_HALF / 128), 256, SMEM_BYTES>>>(
        xh + (size_t)M_HALF * D_MODEL, wq, bqkv,
        qkvh + (size_t)M_HALF * N_QKV, N_QKV);
    attn_mma<<<dim3(T_SEQ / 32, NH, BATCH / 2), 128, ATTN_SMEM>>>(
        qkvh + (size_t)M_HALF * N_QKV, ah + (size_t)M_HALF * D_MODEL);
    gemm_hmma<float><<<dim3(D_MODEL / 256, M_HALF / 128), 256, SMEM_BYTES>>>(
        ah + (size_t)M_HALF * D_MODEL, wo, bout,
        out + (size_t)M_HALF * D_MODEL, D_MODEL);

    cudaStreamWaitEvent(0, evDone, 0);
}

// round 16
// speedup vs baseline: 1.0534x; 1.0534x over previous
#include <cuda_runtime.h>
#include <cuda_fp16.h>
#include <cstdint>
#include <cstring>

#define T_SEQ 2048
#define D_MODEL 1024
#define NH 16
#define HD 64
#define BATCH 4
#define M_TOT (BATCH * T_SEQ)       // 8192
#define N_QKV (3 * D_MODEL)         // 3072
#define M_HALF (M_TOT / 2)          // 4096

// ---------------- scratch (__device__ globals: allocation-free) -------------
__device__ __half g_qkvh[(size_t)M_TOT * N_QKV];        // 48 MB, fp16 qkv
__device__ __half g_xh[(size_t)M_TOT * D_MODEL];
__device__ __half g_wq[(size_t)N_QKV * D_MODEL];
__device__ __half g_wo[(size_t)D_MODEL * D_MODEL];
__device__ __half g_ah[(size_t)M_TOT * D_MODEL];

// ---------------- helpers ---------------------------------------------------
__device__ __forceinline__ uint32_t smem_u32(const void* p) {
    uint32_t a;
    asm("{ .reg .u64 t; cvta.to.shared.u64 t, %1; cvt.u32.u64 %0, t; }"
        : "=r"(a) : "l"(p));
    return a;
}
__device__ __forceinline__ void cp_async16(uint32_t smem_dst, const void* gmem_src) {
    asm volatile("cp.async.cg.shared.global [%0], [%1], 16;"
                 :: "r"(smem_dst), "l"(gmem_src) : "memory");
}
__device__ __forceinline__ void cp_commit() {
    asm volatile("cp.async.commit_group;" ::: "memory");
}
__device__ __forceinline__ void cp_wait1() {
    asm volatile("cp.async.wait_group 1;" ::: "memory");
}
__device__ __forceinline__ void ldsm_x4(uint32_t addr, uint32_t& r0, uint32_t& r1,
                                        uint32_t& r2, uint32_t& r3) {
    asm volatile("ldmatrix.sync.aligned.m8n8.x4.shared.b16 {%0,%1,%2,%3}, [%4];"
                 : "=r"(r0), "=r"(r1), "=r"(r2), "=r"(r3) : "r"(addr));
}
__device__ __forceinline__ void mma_f16(float* d, const uint32_t* a, const uint32_t* b) {
    asm volatile(
        "mma.sync.aligned.m16n8k16.row.col.f32.f16.f16.f32 "
        "{%0,%1,%2,%3}, {%4,%5,%6,%7}, {%8,%9}, {%0,%1,%2,%3};"
        : "+f"(d[0]), "+f"(d[1]), "+f"(d[2]), "+f"(d[3])
        : "r"(a[0]), "r"(a[1]), "r"(a[2]), "r"(a[3]), "r"(b[0]), "r"(b[1]));
}

// ---------------- fp32 -> fp16 converts --------------------------------------
#define NX4 ((M_TOT * D_MODEL) / 4)             // 2097152
#define NWQ4 ((N_QKV * D_MODEL) / 4)            // 786432
#define NWO4 ((D_MODEL * D_MODEL) / 4)          // 262144

__global__ __launch_bounds__(256) void conv_xwq(
    const float* __restrict__ x, const float* __restrict__ wq_in,
    __half* __restrict__ xh, __half* __restrict__ wqh)
{
    int i = blockIdx.x * blockDim.x + threadIdx.x;
    const float* src; __half* dst; int j;
    if (i < NX4)               { src = x;     dst = xh;  j = i; }
    else if (i < NX4 + NWQ4)   { src = wq_in; dst = wqh; j = i - NX4; }
    else return;
    float4 v = ((const float4*)src)[j];
    __half h[4] = {__float2half_rn(v.x), __float2half_rn(v.y),
                   __float2half_rn(v.z), __float2half_rn(v.w)};
    *(uint2*)(dst + 4 * (size_t)j) = *(uint2*)h;
}

__global__ __launch_bounds__(256) void conv_wo(
    const float* __restrict__ wo_in, __half* __restrict__ woh)
{
    int i = blockIdx.x * blockDim.x + threadIdx.x;
    if (i >= NWO4) return;
    float4 v = ((const float4*)wo_in)[i];
    __half h[4] = {__float2half_rn(v.x), __float2half_rn(v.y),
                   __float2half_rn(v.z), __float2half_rn(v.w)};
    *(uint2*)(woh + 4 * (size_t)i) = *(uint2*)h;
}

// ---------------- HMMA GEMM (R9/R12 best config, unchanged) ------------------
#define KC 64
#define LDROW 144
#define TILE_B (128 * LDROW)
#define STAGE_B (2 * TILE_B)
#define SMEM_BYTES (3 * STAGE_B)     // 110592
#define NCHUNK (1024 / KC)

template <typename OT>
__global__ __launch_bounds__(256, 2) void gemm_hmma(
    const __half* __restrict__ A, const __half* __restrict__ Bw,
    const float* __restrict__ bias, OT* __restrict__ C, int N)
{
    extern __shared__ char smem[];
    const int tid  = threadIdx.x;
    const int wid  = tid >> 5, lane = tid & 31;
    const int wm   = wid >> 1, wn = wid & 1;
    const int bn   = blockIdx.x * 128, bm = blockIdx.y * 128;
    const uint32_t sbase = smem_u32(smem);

    const char* gsrc[2];
    gsrc[0] = (const char*)A  + (size_t)bm * 2048;
    gsrc[1] = (const char*)Bw + (size_t)bn * 2048;

    int ld_which[8], ld_row[8], ld_c16[8];
    #pragma unroll
    for (int i = 0; i < 8; i++) {
        int idx = tid + i * 256;
        ld_which[i] = idx >> 10;
        ld_row[i]   = (idx >> 3) & 127;
        ld_c16[i]   = idx & 7;
    }

    auto load_stage = [&](int chunk, int slot) {
        const size_t k0b = (size_t)chunk * (KC * 2);
        uint32_t sdst = sbase + slot * STAGE_B;
        #pragma unroll
        for (int i = 0; i < 8; i++) {
            const char* g = gsrc[ld_which[i]] + (size_t)ld_row[i] * 2048 + k0b + ld_c16[i] * 16;
            uint32_t s = sdst + ld_which[i] * TILE_B + ld_row[i] * LDROW + ld_c16[i] * 16;
            cp_async16(s, g);
        }
    };

    float acc[2][8][4];
    #pragma unroll
    for (int mt = 0; mt < 2; mt++)
        #pragma unroll
        for (int nt = 0; nt < 8; nt++)
            #pragma unroll
            for (int j = 0; j < 4; j++) acc[mt][nt][j] = 0.f;

    const uint32_t a_off = (uint32_t)(wm * 32 + (lane & 15)) * LDROW + (lane >> 4) * 16;
    const uint32_t b_off = (uint32_t)(wn * 64 + ((lane >> 4) & 1) * 8 + (lane & 7)) * LDROW
                         + ((lane >> 3) & 1) * 16;

    load_stage(0, 0); cp_commit();
    load_stage(1, 1); cp_commit();

    uint32_t aa[2][2][4], bb[2][4][4];

    for (int c = 0; c < NCHUNK; c++) {
        const int slot = c % 3;
        cp_wait1();
        __syncthreads();
        if (c + 2 < NCHUNK) load_stage(c + 2, (c + 2) % 3);
        cp_commit();

        const uint32_t st = sbase + slot * STAGE_B;
        const uint32_t tA = st, tB = st + TILE_B;

        #pragma unroll
        for (int mt = 0; mt < 2; mt++)
            ldsm_x4(tA + a_off + (uint32_t)mt * 16 * LDROW,
                    aa[0][mt][0], aa[0][mt][1], aa[0][mt][2], aa[0][mt][3]);
        #pragma unroll
        for (int p = 0; p < 4; p++)
            ldsm_x4(tB + b_off + (uint32_t)p * 16 * LDROW,
                    bb[0][p][0], bb[0][p][1], bb[0][p][2], bb[0][p][3]);

        #pragma unroll
        for (int ks = 0; ks < 4; ks++) {
            const int cur = ks & 1, nxt = cur ^ 1;
            if (ks < 3) {
                const uint32_t kb = (ks + 1) * 32;
                #pragma unroll
                for (int mt = 0; mt < 2; mt++)
                    ldsm_x4(tA + a_off + (uint32_t)mt * 16 * LDROW + kb,
                            aa[nxt][mt][0], aa[nxt][mt][1], aa[nxt][mt][2], aa[nxt][mt][3]);
                #pragma unroll
                for (int p = 0; p < 4; p++)
                    ldsm_x4(tB + b_off + (uint32_t)p * 16 * LDROW + kb,
                            bb[nxt][p][0], bb[nxt][p][1], bb[nxt][p][2], bb[nxt][p][3]);
            }
            #pragma unroll
            for (int mt = 0; mt < 2; mt++)
                #pragma unroll
                for (int nt = 0; nt < 8; nt++)
                    mma_f16(acc[mt][nt], aa[cur][mt], &bb[cur][nt >> 1][(nt & 1) * 2]);
        }
    }
    __syncthreads();

    float* stage = (float*)smem;          // [128][132]
    #pragma unroll
    for (int mt = 0; mt < 2; mt++)
        #pragma unroll
        for (int nt = 0; nt < 8; nt++) {
            int row = wm * 32 + mt * 16 + (lane >> 2);
            int col = wn * 64 + nt * 8 + (lane & 3) * 2;
            stage[row * 132 + col]           = acc[mt][nt][0];
            stage[row * 132 + col + 1]       = acc[mt][nt][1];
            stage[(row + 8) * 132 + col]     = acc[mt][nt][2];
            stage[(row + 8) * 132 + col + 1] = acc[mt][nt][3];
        }
    __syncthreads();

    #pragma unroll
    for (int i = 0; i < 16; i++) {
        int idx = tid + i * 256;
        int row = idx >> 5;
        int c4  = (idx & 31) * 4;
        float4 bv = *(const float4*)(bias + bn + c4);
        float ox = stage[row * 132 + c4 + 0] + bv.x;
        float oy = stage[row * 132 + c4 + 1] + bv.y;
        float oz = stage[row * 132 + c4 + 2] + bv.z;
        float ow = stage[row * 132 + c4 + 3] + bv.w;
        if constexpr (sizeof(OT) == 4) {
            float4 o = {ox, oy, oz, ow};
            *(float4*)((float*)C + (size_t)(bm + row) * N + bn + c4) = o;
        } else {
            __half h4[4] = {__float2half_rn(ox), __float2half_rn(oy),
                            __float2half_rn(oz), __float2half_rn(ow)};
            *(uint2*)((__half*)C + (size_t)(bm + row) * N + bn + c4) = *(uint2*)h4;
        }
    }
}

// ---------------- tensor-core local attention (R11, unchanged) ---------------
#define SQK_B 144
#define SPV_B 208
#define AOFF_Q 0
#define AOFF_K (32 * SQK_B)
#define AOFF_V (AOFF_K + 96 * SQK_B)
#define AOFF_P (AOFF_V + 64 * SPV_B)
#define AOFF_MX (AOFF_P + 32 * SPV_B)
#define AOFF_SM (AOFF_MX + 512)
#define ATTN_SMEM (AOFF_SM + 512)

__global__ __launch_bounds__(128) void attn_mma(
    const __half* __restrict__ qkv, __half* __restrict__ outh)
{
    extern __shared__ char asmem[];
    __half* Qs = (__half*)(asmem + AOFF_Q);
    __half* Ks = (__half*)(asmem + AOFF_K);
    __half* Vt = (__half*)(asmem + AOFF_V);
    __half* Ps = (__half*)(asmem + AOFF_P);
    float* maxp = (float*)(asmem + AOFF_MX);
    float* sump = (float*)(asmem + AOFF_SM);

    const int b = blockIdx.z, h = blockIdx.y;
    const int t0 = blockIdx.x * 32;
    const int kbase = t0 - 32;
    const int tid = threadIdx.x;
    const int w = tid >> 5, lane = tid & 31;
    const uint32_t sb = smem_u32(asmem);

    const __half2 qscale = __float2half2_rn(0.125f);
    #pragma unroll
    for (int i = tid; i < 256; i += 128) {
        int row = i >> 3, c = i & 7;
        uint4 v = ((const uint4*)(qkv + ((size_t)(b * T_SEQ + t0 + row)) * N_QKV
                                  + h * HD))[c];
        __half2 hv[4]; memcpy(hv, &v, 16);
        #pragma unroll
        for (int k = 0; k < 4; k++) hv[k] = __hmul2(hv[k], qscale);
        memcpy(&v, hv, 16);
        *(uint4*)((char*)Qs + row * SQK_B + c * 16) = v;
    }
    #pragma unroll
    for (int i = tid; i < 768; i += 128) {
        int row = i >> 3, c = i & 7;
        int tk = kbase + row;
        uint4 v = {0u, 0u, 0u, 0u};
        if (tk >= 0 && tk < T_SEQ)
            v = ((const uint4*)(qkv + ((size_t)(b * T_SEQ + tk)) * N_QKV
                                + D_MODEL + h * HD))[c];
        *(uint4*)((char*)Ks + row * SQK_B + c * 16) = v;
    }
    #pragma unroll
    for (int i = tid; i < 768; i += 128) {
        int row = i >> 3, c = i & 7;
        int tk = kbase + row;
        uint4 v = {0u, 0u, 0u, 0u};
        if (tk >= 0 && tk < T_SEQ)
            v = ((const uint4*)(qkv + ((size_t)(b * T_SEQ + tk)) * N_QKV
                                + 2 * D_MODEL + h * HD))[c];
        __half hv[8]; memcpy(hv, &v, 16);
        #pragma unroll
        for (int d = 0; d < 8; d++)
            *(__half*)((char*)Vt + (c * 8 + d) * SPV_B + row * 2) = hv[d];
    }
    __syncthreads();

    float sc[2][4][4];
    #pragma unroll
    for (int mt = 0; mt < 2; mt++)
        #pragma unroll
        for (int nt = 0; nt < 4; nt++)
            #pragma unroll
            for (int c = 0; c < 4; c++) sc[mt][nt][c] = 0.f;

    const uint32_t a_off = (uint32_t)(lane & 15) * SQK_B + (lane >> 4) * 16;
    const uint32_t b_off = (uint32_t)(((lane >> 4) & 1) * 8 + (lane & 7)) * SQK_B
                         + ((lane >> 3) & 1) * 16;

    if (w < 3) {
        const uint32_t Qb = sb + AOFF_Q;
        const uint32_t Kb = sb + AOFF_K + (uint32_t)w * 32 * SQK_B;
        #pragma unroll
        for (int ks = 0; ks < 4; ks++) {
            const uint32_t kb = ks * 32;
            uint32_t qa[2][4], kb4[2][4];
            #pragma unroll
            for (int mt = 0; mt < 2; mt++)
                ldsm_x4(Qb + a_off + (uint32_t)mt * 16 * SQK_B + kb,
                        qa[mt][0], qa[mt][1], qa[mt][2], qa[mt][3]);
            #pragma unroll
            for (int p = 0; p < 2; p++)
                ldsm_x4(Kb + b_off + (uint32_t)p * 16 * SQK_B + kb,
                        kb4[p][0], kb4[p][1], kb4[p][2], kb4[p][3]);
            #pragma unroll
            for (int mt = 0; mt < 2; mt++)
                #pragma unroll
                for (int nt = 0; nt < 4; nt++)
                    mma_f16(sc[mt][nt], qa[mt], &kb4[nt >> 1][(nt & 1) * 2]);
        }
    }

    float rmax[4] = {-1e30f, -1e30f, -1e30f, -1e30f};
    if (w < 3) {
        #pragma unroll
        for (int mt = 0; mt < 2; mt++)
            #pragma unroll
            for (int nt = 0; nt < 4; nt++) {
                int j0 = w * 32 + nt * 8 + ((lane & 3) << 1);
                #pragma unroll
                for (int c = 0; c < 4; c++) {
                    int j = j0 + (c & 1);
                    int row = mt * 16 + (c >> 1) * 8 + (lane >> 2);
                    int key = kbase + j;
                    bool ok = (j >= row) && (j <= row + 64) && (key >= 0) && (key < T_SEQ);
                    float s = ok ? sc[mt][nt][c] : -1e30f;
                    sc[mt][nt][c] = s;
                    int ri = mt * 2 + (c >> 1);
                    rmax[ri] = fmaxf(rmax[ri], s);
                }
            }
        #pragma unroll
        for (int ri = 0; ri < 4; ri++) {
            rmax[ri] = fmaxf(rmax[ri], __shfl_xor_sync(0xffffffffu, rmax[ri], 1));
            rmax[ri] = fmaxf(rmax[ri], __shfl_xor_sync(0xffffffffu, rmax[ri], 2));
        }
        if ((lane & 3) == 0)
            #pragma unroll
            for (int ri = 0; ri < 4; ri++) {
                int row = (ri >> 1) * 16 + (ri & 1) * 8 + (lane >> 2);
                maxp[row * 4 + w] = rmax[ri];
            }
    } else {
        if ((lane & 3) == 0)
            #pragma unroll
            for (int ri = 0; ri < 4; ri++) {
                int row = (ri >> 1) * 16 + (ri & 1) * 8 + (lane >> 2);
                maxp[row * 4 + 3] = -1e30f;
                sump[row * 4 + 3] = 0.f;
            }
    }
    __syncthreads();

    float gmx[4], rsum[4] = {0.f, 0.f, 0.f, 0.f};
    #pragma unroll
    for (int ri = 0; ri < 4; ri++) {
        int row = (ri >> 1) * 16 + (ri & 1) * 8 + (lane >> 2);
        float4 mp = *(const float4*)&maxp[row * 4];
        gmx[ri] = fmaxf(fmaxf(mp.x, mp.y), fmaxf(mp.z, mp.w));
    }
    if (w < 3) {
        #pragma unroll
        for (int mt = 0; mt < 2; mt++)
            #pragma unroll
            for (int nt = 0; nt < 4; nt++)
                #pragma unroll
                for (int c = 0; c < 4; c++) {
                    int ri = mt * 2 + (c >> 1);
                    float e = __expf(sc[mt][nt][c] - gmx[ri]);
                    sc[mt][nt][c] = e;
                    rsum[ri] += e;
                }
        #pragma unroll
        for (int ri = 0; ri < 4; ri++) {
            rsum[ri] += __shfl_xor_sync(0xffffffffu, rsum[ri], 1);
            rsum[ri] += __shfl_xor_sync(0xffffffffu, rsum[ri], 2);
        }
        if ((lane & 3) == 0)
            #pragma unroll
            for (int ri = 0; ri < 4; ri++) {
                int row = (ri >> 1) * 16 + (ri & 1) * 8 + (lane >> 2);
                sump[row * 4 + w] = rsum[ri];
            }
    }
    __syncthreads();

    if (w < 3) {
        float inv[4];
        #pragma unroll
        for (int ri = 0; ri < 4; ri++) {
            int row = (ri >> 1) * 16 + (ri & 1) * 8 + (lane >> 2);
            float4 sp = *(const float4*)&sump[row * 4];
            inv[ri] = 1.f / (sp.x + sp.y + sp.z + sp.w);
        }
        #pragma unroll
        for (int mt = 0; mt < 2; mt++)
            #pragma unroll
            for (int nt = 0; nt < 4; nt++) {
                int j0 = w * 32 + nt * 8 + ((lane & 3) << 1);
                int rowA = mt * 16 + (lane >> 2);
                __half2 pA = __floats2half2_rn(sc[mt][nt][0] * inv[mt * 2],
                                               sc[mt][nt][1] * inv[mt * 2]);
                __half2 pB = __floats2half2_rn(sc[mt][nt][2] * inv[mt * 2 + 1],
                                               sc[mt][nt][3] * inv[mt * 2 + 1]);
                *(__half2*)((char*)Ps + rowA * SPV_B + j0 * 2) = pA;
                *(__half2*)((char*)Ps + (rowA + 8) * SPV_B + j0 * 2) = pB;
            }
    }
    __syncthreads();

    float oc[2][2][4];
    #pragma unroll
    for (int mt = 0; mt < 2; mt++)
        #pragma unroll
        for (int nt = 0; nt < 2; nt++)
            #pragma unroll
            for (int c = 0; c < 4; c++) oc[mt][nt][c] = 0.f;

    const uint32_t Pb = sb + AOFF_P;
    const uint32_t Vb = sb + AOFF_V + (uint32_t)w * 16 * SPV_B;
    const uint32_t a_offP = (uint32_t)(lane & 15) * SPV_B + (lane >> 4) * 16;
    const uint32_t b_offV = (uint32_t)(((lane >> 4) & 1) * 8 + (lane & 7)) * SPV_B
                          + ((lane >> 3) & 1) * 16;

    #pragma unroll
    for (int ks = 0; ks < 6; ks++) {
        const uint32_t kb = ks * 32;
        uint32_t pa[2][4], vb[4];
        #pragma unroll
        for (int mt = 0; mt < 2; mt++)
            ldsm_x4(Pb + a_offP + (uint32_t)mt * 16 * SPV_B + kb,
                    pa[mt][0], pa[mt][1], pa[mt][2], pa[mt][3]);
        ldsm_x4(Vb + b_offV + kb, vb[0], vb[1], vb[2], vb[3]);
        #pragma unroll
        for (int mt = 0; mt < 2; mt++)
            #pragma unroll
            for (int nt = 0; nt < 2; nt++)
                mma_f16(oc[mt][nt], pa[mt], &vb[nt * 2]);
    }

    const size_t base = ((size_t)(b * T_SEQ + t0)) * D_MODEL + h * HD;
    #pragma unroll
    for (int mt = 0; mt < 2; mt++)
        #pragma unroll
        for (int nt = 0; nt < 2; nt++) {
            int rowA = mt * 16 + (lane >> 2);
            int col = w * 16 + nt * 8 + ((lane & 3) << 1);
            __half2 hA = __floats2half2_rn(oc[mt][nt][0], oc[mt][nt][1]);
            __half2 hB = __floats2half2_rn(oc[mt][nt][2], oc[mt][nt][3]);
            *(__half2*)(outh + base + (size_t)rowA * D_MODEL + col) = hA;
            *(__half2*)(outh + base + (size_t)(rowA + 8) * D_MODEL + col) = hB;
        }
}

// ---------------------------------------------------------------------------
extern "C" void kernel_launch(void* const* d_in, const int* in_sizes, int n_in,
                              void* d_out, int out_size)
{
    const float* x    = (const float*)d_in[0];
    const float* Wqkv = (const float*)d_in[1];
    const float* bqkv = (const float*)d_in[2];
    const float* Wout = (const float*)d_in[3];
    const float* bout = (const float*)d_in[4];
    float* out = (float*)d_out;

    __half *qkvh, *xh, *wq, *wo, *ah;
    cudaGetSymbolAddress((void**)&qkvh, g_qkvh);
    cudaGetSymbolAddress((void**)&xh, g_xh);
    cudaGetSymbolAddress((void**)&wq, g_wq);
    cudaGetSymbolAddress((void**)&wo, g_wo);
    cudaGetSymbolAddress((void**)&ah, g_ah);

    cudaFuncSetAttribute(gemm_hmma<__half>, cudaFuncAttributeMaxDynamicSharedMemorySize, SMEM_BYTES);
    cudaFuncSetAttribute(gemm_hmma<float>,  cudaFuncAttributeMaxDynamicSharedMemorySize, SMEM_BYTES);
    cudaFuncSetAttribute(attn_mma, cudaFuncAttributeMaxDynamicSharedMemorySize, ATTN_SMEM);

    static cudaStream_t s1 = nullptr;
    static cudaEvent_t evFork = nullptr, evA = nullptr, evWo = nullptr, evDone = nullptr;
    if (s1 == nullptr) {
        cudaStreamCreateWithFlags(&s1, cudaStreamNonBlocking);
        cudaEventCreateWithFlags(&evFork, cudaEventDisableTiming);
        cudaEventCreateWithFlags(&evA, cudaEventDisableTiming);
        cudaEventCreateWithFlags(&evWo, cudaEventDisableTiming);
        cudaEventCreateWithFlags(&evDone, cudaEventDisableTiming);
    }

    // Fork s1 from the capture stream FIRST (required during graph capture:
    // a side stream must be event-forked before it receives launches).
    cudaEventRecord(evFork, 0);
    cudaStreamWaitEvent(s1, evFork, 0);

    // s1: Wout conversion, concurrent with s0's conv + QKV half A
    conv_wo<<<(NWO4 + 255) / 256, 256, 0, s1>>>(Wout, wo);
    cudaEventRecord(evWo, s1);

    // s0: x + Wqkv conversion (QKV's true dependency)
    {
        int total = NX4 + NWQ4;
        conv_xwq<<<(total + 255) / 256, 256>>>(x, Wqkv, xh, wq);
    }

    // QKV half A (rows 0..4095)
    gemm_hmma<__half><<<dim3(N_QKV / 128, M_HALF / 128), 256, SMEM_BYTES>>>(
        xh, wq, bqkv, qkvh, N_QKV);
    cudaEventRecord(evA, 0);

    // s1: attention + out-proj for half A (wo already ready on s1's own chain)
    cudaStreamWaitEvent(s1, evA, 0);
    attn_mma<<<dim3(T_SEQ / 32, NH, BATCH / 2), 128, ATTN_SMEM, s1>>>(qkvh, ah);
    gemm_hmma<float><<<dim3(D_MODEL / 128, M_HALF / 128), 256, SMEM_BYTES, s1>>>(
        ah, wo, bout, out, D_MODEL);
    cudaEventRecord(evDone, s1);

    // s0: QKV half B, then its attention + out-proj (wait evWo for wo)
    gemm_hmma<__half><<<dim3(N_QKV / 128, M_HALF / 128), 256, SMEM_BYTES>>>(
        xh + (size_t)M_HALF * D_MODEL, wq, bqkv,
        qkvh + (size_t)M_HALF * N_QKV, N_QKV);
    attn_mma<<<dim3(T_SEQ / 32, NH, BATCH / 2), 128, ATTN_SMEM>>>(
        qkvh + (size_t)M_HALF * N_QKV, ah + (size_t)M_HALF * D_MODEL);
    cudaStreamWaitEvent(0, evWo, 0);
    gemm_hmma<float><<<dim3(D_MODEL / 128, M_HALF / 128), 256, SMEM_BYTES>>>(
        ah + (size_t)M_HALF * D_MODEL, wo, bout,
        out + (size_t)M_HALF * D_MODEL, D_MODEL);

    cudaStreamWaitEvent(0, evDone, 0);
}

// round 17
// speedup vs baseline: 1.0754x; 1.0209x over previous
#include <cuda_runtime.h>
#include <cuda_fp16.h>
#include <cstdint>
#include <cstring>

#define T_SEQ 2048
#define D_MODEL 1024
#define NH 16
#define HD 64
#define BATCH 4
#define M_TOT (BATCH * T_SEQ)       // 8192
#define N_QKV (3 * D_MODEL)         // 3072
#define M_HALF (M_TOT / 2)          // 4096

// ---------------- scratch (__device__ globals: allocation-free) -------------
__device__ __half g_qkvh[(size_t)M_TOT * N_QKV];        // 48 MB, fp16 qkv
__device__ __half g_xh[(size_t)M_TOT * D_MODEL];
__device__ __half g_wq[(size_t)N_QKV * D_MODEL];
__device__ __half g_wo[(size_t)D_MODEL * D_MODEL];
__device__ __half g_ah[(size_t)M_TOT * D_MODEL];

// ---------------- helpers ---------------------------------------------------
__device__ __forceinline__ uint32_t smem_u32(const void* p) {
    uint32_t a;
    asm("{ .reg .u64 t; cvta.to.shared.u64 t, %1; cvt.u32.u64 %0, t; }"
        : "=r"(a) : "l"(p));
    return a;
}
__device__ __forceinline__ void cp_async16(uint32_t smem_dst, const void* gmem_src) {
    asm volatile("cp.async.cg.shared.global [%0], [%1], 16;"
                 :: "r"(smem_dst), "l"(gmem_src) : "memory");
}
__device__ __forceinline__ void cp_commit() {
    asm volatile("cp.async.commit_group;" ::: "memory");
}
__device__ __forceinline__ void cp_wait1() {
    asm volatile("cp.async.wait_group 1;" ::: "memory");
}
__device__ __forceinline__ void ldsm_x4(uint32_t addr, uint32_t& r0, uint32_t& r1,
                                        uint32_t& r2, uint32_t& r3) {
    asm volatile("ldmatrix.sync.aligned.m8n8.x4.shared.b16 {%0,%1,%2,%3}, [%4];"
                 : "=r"(r0), "=r"(r1), "=r"(r2), "=r"(r3) : "r"(addr));
}
__device__ __forceinline__ void mma_f16(float* d, const uint32_t* a, const uint32_t* b) {
    asm volatile(
        "mma.sync.aligned.m16n8k16.row.col.f32.f16.f16.f32 "
        "{%0,%1,%2,%3}, {%4,%5,%6,%7}, {%8,%9}, {%0,%1,%2,%3};"
        : "+f"(d[0]), "+f"(d[1]), "+f"(d[2]), "+f"(d[3])
        : "r"(a[0]), "r"(a[1]), "r"(a[2]), "r"(a[3]), "r"(b[0]), "r"(b[1]));
}

// ---------------- fp32 -> fp16 converts --------------------------------------
#define NX4 ((M_TOT * D_MODEL) / 4)             // 2097152
#define NWQ4 ((N_QKV * D_MODEL) / 4)            // 786432
#define NWO4 ((D_MODEL * D_MODEL) / 4)          // 262144

__global__ __launch_bounds__(256) void conv_xwq(
    const float* __restrict__ x, const float* __restrict__ wq_in,
    __half* __restrict__ xh, __half* __restrict__ wqh)
{
    int i = blockIdx.x * blockDim.x + threadIdx.x;
    const float* src; __half* dst; int j;
    if (i < NX4)               { src = x;     dst = xh;  j = i; }
    else if (i < NX4 + NWQ4)   { src = wq_in; dst = wqh; j = i - NX4; }
    else return;
    float4 v = ((const float4*)src)[j];
    __half h[4] = {__float2half_rn(v.x), __float2half_rn(v.y),
                   __float2half_rn(v.z), __float2half_rn(v.w)};
    *(uint2*)(dst + 4 * (size_t)j) = *(uint2*)h;
}

__global__ __launch_bounds__(256) void conv_wo(
    const float* __restrict__ wo_in, __half* __restrict__ woh)
{
    int i = blockIdx.x * blockDim.x + threadIdx.x;
    if (i >= NWO4) return;
    float4 v = ((const float4*)wo_in)[i];
    __half h[4] = {__float2half_rn(v.x), __float2half_rn(v.y),
                   __float2half_rn(v.z), __float2half_rn(v.w)};
    *(uint2*)(woh + 4 * (size_t)i) = *(uint2*)h;
}

// ---------------- HMMA GEMM (R9/R12 best config, unchanged) ------------------
#define KC 64
#define LDROW 144
#define TILE_B (128 * LDROW)
#define STAGE_B (2 * TILE_B)
#define SMEM_BYTES (3 * STAGE_B)     // 110592
#define NCHUNK (1024 / KC)

template <typename OT>
__global__ __launch_bounds__(256, 2) void gemm_hmma(
    const __half* __restrict__ A, const __half* __restrict__ Bw,
    const float* __restrict__ bias, OT* __restrict__ C, int N)
{
    extern __shared__ char smem[];
    const int tid  = threadIdx.x;
    const int wid  = tid >> 5, lane = tid & 31;
    const int wm   = wid >> 1, wn = wid & 1;
    const int bn   = blockIdx.x * 128, bm = blockIdx.y * 128;
    const uint32_t sbase = smem_u32(smem);

    const char* gsrc[2];
    gsrc[0] = (const char*)A  + (size_t)bm * 2048;
    gsrc[1] = (const char*)Bw + (size_t)bn * 2048;

    int ld_which[8], ld_row[8], ld_c16[8];
    #pragma unroll
    for (int i = 0; i < 8; i++) {
        int idx = tid + i * 256;
        ld_which[i] = idx >> 10;
        ld_row[i]   = (idx >> 3) & 127;
        ld_c16[i]   = idx & 7;
    }

    auto load_stage = [&](int chunk, int slot) {
        const size_t k0b = (size_t)chunk * (KC * 2);
        uint32_t sdst = sbase + slot * STAGE_B;
        #pragma unroll
        for (int i = 0; i < 8; i++) {
            const char* g = gsrc[ld_which[i]] + (size_t)ld_row[i] * 2048 + k0b + ld_c16[i] * 16;
            uint32_t s = sdst + ld_which[i] * TILE_B + ld_row[i] * LDROW + ld_c16[i] * 16;
            cp_async16(s, g);
        }
    };

    float acc[2][8][4];
    #pragma unroll
    for (int mt = 0; mt < 2; mt++)
        #pragma unroll
        for (int nt = 0; nt < 8; nt++)
            #pragma unroll
            for (int j = 0; j < 4; j++) acc[mt][nt][j] = 0.f;

    const uint32_t a_off = (uint32_t)(wm * 32 + (lane & 15)) * LDROW + (lane >> 4) * 16;
    const uint32_t b_off = (uint32_t)(wn * 64 + ((lane >> 4) & 1) * 8 + (lane & 7)) * LDROW
                         + ((lane >> 3) & 1) * 16;

    load_stage(0, 0); cp_commit();
    load_stage(1, 1); cp_commit();

    uint32_t aa[2][2][4], bb[2][4][4];

    for (int c = 0; c < NCHUNK; c++) {
        const int slot = c % 3;
        cp_wait1();
        __syncthreads();
        if (c + 2 < NCHUNK) load_stage(c + 2, (c + 2) % 3);
        cp_commit();

        const uint32_t st = sbase + slot * STAGE_B;
        const uint32_t tA = st, tB = st + TILE_B;

        #pragma unroll
        for (int mt = 0; mt < 2; mt++)
            ldsm_x4(tA + a_off + (uint32_t)mt * 16 * LDROW,
                    aa[0][mt][0], aa[0][mt][1], aa[0][mt][2], aa[0][mt][3]);
        #pragma unroll
        for (int p = 0; p < 4; p++)
            ldsm_x4(tB + b_off + (uint32_t)p * 16 * LDROW,
                    bb[0][p][0], bb[0][p][1], bb[0][p][2], bb[0][p][3]);

        #pragma unroll
        for (int ks = 0; ks < 4; ks++) {
            const int cur = ks & 1, nxt = cur ^ 1;
            if (ks < 3) {
                const uint32_t kb = (ks + 1) * 32;
                #pragma unroll
                for (int mt = 0; mt < 2; mt++)
                    ldsm_x4(tA + a_off + (uint32_t)mt * 16 * LDROW + kb,
                            aa[nxt][mt][0], aa[nxt][mt][1], aa[nxt][mt][2], aa[nxt][mt][3]);
                #pragma unroll
                for (int p = 0; p < 4; p++)
                    ldsm_x4(tB + b_off + (uint32_t)p * 16 * LDROW + kb,
                            bb[nxt][p][0], bb[nxt][p][1], bb[nxt][p][2], bb[nxt][p][3]);
            }
            #pragma unroll
            for (int mt = 0; mt < 2; mt++)
                #pragma unroll
                for (int nt = 0; nt < 8; nt++)
                    mma_f16(acc[mt][nt], aa[cur][mt], &bb[cur][nt >> 1][(nt & 1) * 2]);
        }
    }
    __syncthreads();

    float* stage = (float*)smem;          // [128][132]
    #pragma unroll
    for (int mt = 0; mt < 2; mt++)
        #pragma unroll
        for (int nt = 0; nt < 8; nt++) {
            int row = wm * 32 + mt * 16 + (lane >> 2);
            int col = wn * 64 + nt * 8 + (lane & 3) * 2;
            stage[row * 132 + col]           = acc[mt][nt][0];
            stage[row * 132 + col + 1]       = acc[mt][nt][1];
            stage[(row + 8) * 132 + col]     = acc[mt][nt][2];
            stage[(row + 8) * 132 + col + 1] = acc[mt][nt][3];
        }
    __syncthreads();

    #pragma unroll
    for (int i = 0; i < 16; i++) {
        int idx = tid + i * 256;
        int row = idx >> 5;
        int c4  = (idx & 31) * 4;
        float4 bv = *(const float4*)(bias + bn + c4);
        float ox = stage[row * 132 + c4 + 0] + bv.x;
        float oy = stage[row * 132 + c4 + 1] + bv.y;
        float oz = stage[row * 132 + c4 + 2] + bv.z;
        float ow = stage[row * 132 + c4 + 3] + bv.w;
        if constexpr (sizeof(OT) == 4) {
            float4 o = {ox, oy, oz, ow};
            *(float4*)((float*)C + (size_t)(bm + row) * N + bn + c4) = o;
        } else {
            __half h4[4] = {__float2half_rn(ox), __float2half_rn(oy),
                            __float2half_rn(oz), __float2half_rn(ow)};
            *(uint2*)((__half*)C + (size_t)(bm + row) * N + bn + c4) = *(uint2*)h4;
        }
    }
}

// ---------------- tensor-core local attention --------------------------------
// R11 structure; V->Vt transpose staging rewritten: 4 keys per STS.64 with
// rotated store order (conflict-free), cutting V staging STS count 4x.
#define SQK_B 144
#define SPV_B 208
#define AOFF_Q 0
#define AOFF_K (32 * SQK_B)
#define AOFF_V (AOFF_K + 96 * SQK_B)
#define AOFF_P (AOFF_V + 64 * SPV_B)
#define AOFF_MX (AOFF_P + 32 * SPV_B)
#define AOFF_SM (AOFF_MX + 512)
#define ATTN_SMEM (AOFF_SM + 512)

__global__ __launch_bounds__(128) void attn_mma(
    const __half* __restrict__ qkv, __half* __restrict__ outh)
{
    extern __shared__ char asmem[];
    __half* Qs = (__half*)(asmem + AOFF_Q);
    __half* Ks = (__half*)(asmem + AOFF_K);
    __half* Vt = (__half*)(asmem + AOFF_V);
    __half* Ps = (__half*)(asmem + AOFF_P);
    float* maxp = (float*)(asmem + AOFF_MX);
    float* sump = (float*)(asmem + AOFF_SM);

    const int b = blockIdx.z, h = blockIdx.y;
    const int t0 = blockIdx.x * 32;
    const int kbase = t0 - 32;
    const int tid = threadIdx.x;
    const int w = tid >> 5, lane = tid & 31;
    const uint32_t sb = smem_u32(asmem);

    const __half2 qscale = __float2half2_rn(0.125f);
    #pragma unroll
    for (int i = tid; i < 256; i += 128) {       // Q (pre-scaled)
        int row = i >> 3, c = i & 7;
        uint4 v = ((const uint4*)(qkv + ((size_t)(b * T_SEQ + t0 + row)) * N_QKV
                                  + h * HD))[c];
        __half2 hv[4]; memcpy(hv, &v, 16);
        #pragma unroll
        for (int k = 0; k < 4; k++) hv[k] = __hmul2(hv[k], qscale);
        memcpy(&v, hv, 16);
        *(uint4*)((char*)Qs + row * SQK_B + c * 16) = v;
    }
    #pragma unroll
    for (int i = tid; i < 768; i += 128) {       // K
        int row = i >> 3, c = i & 7;
        int tk = kbase + row;
        uint4 v = {0u, 0u, 0u, 0u};
        if (tk >= 0 && tk < T_SEQ)
            v = ((const uint4*)(qkv + ((size_t)(b * T_SEQ + tk)) * N_QKV
                                + D_MODEL + h * HD))[c];
        *(uint4*)((char*)Ks + row * SQK_B + c * 16) = v;
    }
    // V -> Vt transpose: 4 keys per task, one STS.64 per dim, rotated order.
    #pragma unroll
    for (int i = tid; i < 192; i += 128) {
        int row4 = i >> 3, c = i & 7;            // row4: 4-key group, c: dim chunk
        uint4 vr[4];
        #pragma unroll
        for (int j = 0; j < 4; j++) {
            int tk = kbase + row4 * 4 + j;
            uint4 v = {0u, 0u, 0u, 0u};
            if (tk >= 0 && tk < T_SEQ)
                v = ((const uint4*)(qkv + ((size_t)(b * T_SEQ + tk)) * N_QKV
                                    + 2 * D_MODEL + h * HD))[c];
            vr[j] = v;
        }
        __half hv[4][8];
        memcpy(hv[0], &vr[0], 16); memcpy(hv[1], &vr[1], 16);
        memcpy(hv[2], &vr[2], 16); memcpy(hv[3], &vr[3], 16);
        #pragma unroll
        for (int dd = 0; dd < 8; dd++) {
            int d = (dd + c) & 7;                // rotation -> conflict-free STS.64
            __half q4[4] = {hv[0][d], hv[1][d], hv[2][d], hv[3][d]};
            *(uint2*)((char*)Vt + (c * 8 + d) * SPV_B + row4 * 8) = *(uint2*)q4;
        }
    }
    __syncthreads();

    float sc[2][4][4];
    #pragma unroll
    for (int mt = 0; mt < 2; mt++)
        #pragma unroll
        for (int nt = 0; nt < 4; nt++)
            #pragma unroll
            for (int c = 0; c < 4; c++) sc[mt][nt][c] = 0.f;

    const uint32_t a_off = (uint32_t)(lane & 15) * SQK_B + (lane >> 4) * 16;
    const uint32_t b_off = (uint32_t)(((lane >> 4) & 1) * 8 + (lane & 7)) * SQK_B
                         + ((lane >> 3) & 1) * 16;

    if (w < 3) {
        const uint32_t Qb = sb + AOFF_Q;
        const uint32_t Kb = sb + AOFF_K + (uint32_t)w * 32 * SQK_B;
        #pragma unroll
        for (int ks = 0; ks < 4; ks++) {
            const uint32_t kb = ks * 32;
            uint32_t qa[2][4], kb4[2][4];
            #pragma unroll
            for (int mt = 0; mt < 2; mt++)
                ldsm_x4(Qb + a_off + (uint32_t)mt * 16 * SQK_B + kb,
                        qa[mt][0], qa[mt][1], qa[mt][2], qa[mt][3]);
            #pragma unroll
            for (int p = 0; p < 2; p++)
                ldsm_x4(Kb + b_off + (uint32_t)p * 16 * SQK_B + kb,
                        kb4[p][0], kb4[p][1], kb4[p][2], kb4[p][3]);
            #pragma unroll
            for (int mt = 0; mt < 2; mt++)
                #pragma unroll
                for (int nt = 0; nt < 4; nt++)
                    mma_f16(sc[mt][nt], qa[mt], &kb4[nt >> 1][(nt & 1) * 2]);
        }
    }

    float rmax[4] = {-1e30f, -1e30f, -1e30f, -1e30f};
    if (w < 3) {
        #pragma unroll
        for (int mt = 0; mt < 2; mt++)
            #pragma unroll
            for (int nt = 0; nt < 4; nt++) {
                int j0 = w * 32 + nt * 8 + ((lane & 3) << 1);
                #pragma unroll
                for (int c = 0; c < 4; c++) {
                    int j = j0 + (c & 1);
                    int row = mt * 16 + (c >> 1) * 8 + (lane >> 2);
                    int key = kbase + j;
                    bool ok = (j >= row) && (j <= row + 64) && (key >= 0) && (key < T_SEQ);
                    float s = ok ? sc[mt][nt][c] : -1e30f;
                    sc[mt][nt][c] = s;
                    int ri = mt * 2 + (c >> 1);
                    rmax[ri] = fmaxf(rmax[ri], s);
                }
            }
        #pragma unroll
        for (int ri = 0; ri < 4; ri++) {
            rmax[ri] = fmaxf(rmax[ri], __shfl_xor_sync(0xffffffffu, rmax[ri], 1));
            rmax[ri] = fmaxf(rmax[ri], __shfl_xor_sync(0xffffffffu, rmax[ri], 2));
        }
        if ((lane & 3) == 0)
            #pragma unroll
            for (int ri = 0; ri < 4; ri++) {
                int row = (ri >> 1) * 16 + (ri & 1) * 8 + (lane >> 2);
                maxp[row * 4 + w] = rmax[ri];
            }
    } else {
        if ((lane & 3) == 0)
            #pragma unroll
            for (int ri = 0; ri < 4; ri++) {
                int row = (ri >> 1) * 16 + (ri & 1) * 8 + (lane >> 2);
                maxp[row * 4 + 3] = -1e30f;
                sump[row * 4 + 3] = 0.f;
            }
    }
    __syncthreads();

    float gmx[4], rsum[4] = {0.f, 0.f, 0.f, 0.f};
    #pragma unroll
    for (int ri = 0; ri < 4; ri++) {
        int row = (ri >> 1) * 16 + (ri & 1) * 8 + (lane >> 2);
        float4 mp = *(const float4*)&maxp[row * 4];
        gmx[ri] = fmaxf(fmaxf(mp.x, mp.y), fmaxf(mp.z, mp.w));
    }
    if (w < 3) {
        #pragma unroll
        for (int mt = 0; mt < 2; mt++)
            #pragma unroll
            for (int nt = 0; nt < 4; nt++)
                #pragma unroll
                for (int c = 0; c < 4; c++) {
                    int ri = mt * 2 + (c >> 1);
                    float e = __expf(sc[mt][nt][c] - gmx[ri]);
                    sc[mt][nt][c] = e;
                    rsum[ri] += e;
                }
        #pragma unroll
        for (int ri = 0; ri < 4; ri++) {
            rsum[ri] += __shfl_xor_sync(0xffffffffu, rsum[ri], 1);
            rsum[ri] += __shfl_xor_sync(0xffffffffu, rsum[ri], 2);
        }
        if ((lane & 3) == 0)
            #pragma unroll
            for (int ri = 0; ri < 4; ri++) {
                int row = (ri >> 1) * 16 + (ri & 1) * 8 + (lane >> 2);
                sump[row * 4 + w] = rsum[ri];
            }
    }
    __syncthreads();

    if (w < 3) {
        float inv[4];
        #pragma unroll
        for (int ri = 0; ri < 4; ri++) {
            int row = (ri >> 1) * 16 + (ri & 1) * 8 + (lane >> 2);
            float4 sp = *(const float4*)&sump[row * 4];
            inv[ri] = 1.f / (sp.x + sp.y + sp.z + sp.w);
        }
        #pragma unroll
        for (int mt = 0; mt < 2; mt++)
            #pragma unroll
            for (int nt = 0; nt < 4; nt++) {
                int j0 = w * 32 + nt * 8 + ((lane & 3) << 1);
                int rowA = mt * 16 + (lane >> 2);
                __half2 pA = __floats2half2_rn(sc[mt][nt][0] * inv[mt * 2],
                                               sc[mt][nt][1] * inv[mt * 2]);
                __half2 pB = __floats2half2_rn(sc[mt][nt][2] * inv[mt * 2 + 1],
                                               sc[mt][nt][3] * inv[mt * 2 + 1]);
                *(__half2*)((char*)Ps + rowA * SPV_B + j0 * 2) = pA;
                *(__half2*)((char*)Ps + (rowA + 8) * SPV_B + j0 * 2) = pB;
            }
    }
    __syncthreads();

    float oc[2][2][4];
    #pragma unroll
    for (int mt = 0; mt < 2; mt++)
        #pragma unroll
        for (int nt = 0; nt < 2; nt++)
            #pragma unroll
            for (int c = 0; c < 4; c++) oc[mt][nt][c] = 0.f;

    const uint32_t Pb = sb + AOFF_P;
    const uint32_t Vb = sb + AOFF_V + (uint32_t)w * 16 * SPV_B;
    const uint32_t a_offP = (uint32_t)(lane & 15) * SPV_B + (lane >> 4) * 16;
    const uint32_t b_offV = (uint32_t)(((lane >> 4) & 1) * 8 + (lane & 7)) * SPV_B
                          + ((lane >> 3) & 1) * 16;

    #pragma unroll
    for (int ks = 0; ks < 6; ks++) {
        const uint32_t kb = ks * 32;
        uint32_t pa[2][4], vb[4];
        #pragma unroll
        for (int mt = 0; mt < 2; mt++)
            ldsm_x4(Pb + a_offP + (uint32_t)mt * 16 * SPV_B + kb,
                    pa[mt][0], pa[mt][1], pa[mt][2], pa[mt][3]);
        ldsm_x4(Vb + b_offV + kb, vb[0], vb[1], vb[2], vb[3]);
        #pragma unroll
        for (int mt = 0; mt < 2; mt++)
            #pragma unroll
            for (int nt = 0; nt < 2; nt++)
                mma_f16(oc[mt][nt], pa[mt], &vb[nt * 2]);
    }

    const size_t base = ((size_t)(b * T_SEQ + t0)) * D_MODEL + h * HD;
    #pragma unroll
    for (int mt = 0; mt < 2; mt++)
        #pragma unroll
        for (int nt = 0; nt < 2; nt++) {
            int rowA = mt * 16 + (lane >> 2);
            int col = w * 16 + nt * 8 + ((lane & 3) << 1);
            __half2 hA = __floats2half2_rn(oc[mt][nt][0], oc[mt][nt][1]);
            __half2 hB = __floats2half2_rn(oc[mt][nt][2], oc[mt][nt][3]);
            *(__half2*)(outh + base + (size_t)rowA * D_MODEL + col) = hA;
            *(__half2*)(outh + base + (size_t)(rowA + 8) * D_MODEL + col) = hB;
        }
}

// ---------------------------------------------------------------------------
extern "C" void kernel_launch(void* const* d_in, const int* in_sizes, int n_in,
                              void* d_out, int out_size)
{
    const float* x    = (const float*)d_in[0];
    const float* Wqkv = (const float*)d_in[1];
    const float* bqkv = (const float*)d_in[2];
    const float* Wout = (const float*)d_in[3];
    const float* bout = (const float*)d_in[4];
    float* out = (float*)d_out;

    __half *qkvh, *xh, *wq, *wo, *ah;
    cudaGetSymbolAddress((void**)&qkvh, g_qkvh);
    cudaGetSymbolAddress((void**)&xh, g_xh);
    cudaGetSymbolAddress((void**)&wq, g_wq);
    cudaGetSymbolAddress((void**)&wo, g_wo);
    cudaGetSymbolAddress((void**)&ah, g_ah);

    cudaFuncSetAttribute(gemm_hmma<__half>, cudaFuncAttributeMaxDynamicSharedMemorySize, SMEM_BYTES);
    cudaFuncSetAttribute(gemm_hmma<float>,  cudaFuncAttributeMaxDynamicSharedMemorySize, SMEM_BYTES);
    cudaFuncSetAttribute(attn_mma, cudaFuncAttributeMaxDynamicSharedMemorySize, ATTN_SMEM);

    static cudaStream_t s1 = nullptr;
    static cudaEvent_t evFork = nullptr, evA = nullptr, evWo = nullptr, evDone = nullptr;
    if (s1 == nullptr) {
        cudaStreamCreateWithFlags(&s1, cudaStreamNonBlocking);
        cudaEventCreateWithFlags(&evFork, cudaEventDisableTiming);
        cudaEventCreateWithFlags(&evA, cudaEventDisableTiming);
        cudaEventCreateWithFlags(&evWo, cudaEventDisableTiming);
        cudaEventCreateWithFlags(&evDone, cudaEventDisableTiming);
    }

    // Fork s1 from the capture stream first (graph-capture requirement).
    cudaEventRecord(evFork, 0);
    cudaStreamWaitEvent(s1, evFork, 0);

    // s1: Wout conversion, concurrent with s0's conv + QKV half A
    conv_wo<<<(NWO4 + 255) / 256, 256, 0, s1>>>(Wout, wo);
    cudaEventRecord(evWo, s1);

    // s0: x + Wqkv conversion (QKV's true dependency)
    {
        int total = NX4 + NWQ4;
        conv_xwq<<<(total + 255) / 256, 256>>>(x, Wqkv, xh, wq);
    }

    // QKV half A (rows 0..4095)
    gemm_hmma<__half><<<dim3(N_QKV / 128, M_HALF / 128), 256, SMEM_BYTES>>>(
        xh, wq, bqkv, qkvh, N_QKV);
    cudaEventRecord(evA, 0);

    // s1: attention + out-proj for half A (wo ready on s1's own chain)
    cudaStreamWaitEvent(s1, evA, 0);
    attn_mma<<<dim3(T_SEQ / 32, NH, BATCH / 2), 128, ATTN_SMEM, s1>>>(qkvh, ah);
    gemm_hmma<float><<<dim3(D_MODEL / 128, M_HALF / 128), 256, SMEM_BYTES, s1>>>(
        ah, wo, bout, out, D_MODEL);
    cudaEventRecord(evDone, s1);

    // s0: QKV half B, then its attention + out-proj (wait evWo for wo)
    gemm_hmma<__half><<<dim3(N_QKV / 128, M_HALF / 128), 256, SMEM_BYTES>>>(
        xh + (size_t)M_HALF * D_MODEL, wq, bqkv,
        qkvh + (size_t)M_HALF * N_QKV, N_QKV);
    attn_mma<<<dim3(T_SEQ / 32, NH, BATCH / 2), 128, ATTN_SMEM>>>(
        qkvh + (size_t)M_HALF * N_QKV, ah + (size_t)M_HALF * D_MODEL);
    cudaStreamWaitEvent(0, evWo, 0);
    gemm_hmma<float><<<dim3(D_MODEL / 128, M_HALF / 128), 256, SMEM_BYTES>>>(
        ah + (size_t)M_HALF * D_MODEL, wo, bout,
        out + (size_t)M_HALF * D_MODEL, D_MODEL);

    cudaStreamWaitEvent(0, evDone, 0);
}